// round 4
// baseline (speedup 1.0000x reference)
#include <cuda_runtime.h>
#include <math.h>

#define NB 32
#define NT 1024
#define ND 256
#define NROWS (NB*NT)

// -------- scratch (device globals; no allocation) --------
__device__ float g_e[NROWS*ND];   // projected+normalized eeg (scaled by 1/TEMP)
__device__ float g_v[NROWS*ND];   // projected+normalized eye
__device__ int   g_rank[NROWS];   // compressed rank per (b,t)
__device__ float g_row[NROWS];    // per-row masked loss

// Load NR rows (each 256 floats, row stride 256) from src into transposed
// smem tile dst[k][r] with row stride NR. Warp-lane mapping (8 rows x 4 quads
// per warp) keeps global loads coalesced (64B chunks) and limits the STS
// transpose conflict to 4-way.
template<int NR>
__device__ __forceinline__ void load_tile_T(float* __restrict__ dst,
                                            const float* __restrict__ src,
                                            int tid) {
    const int lane = tid & 31;
    const int w    = tid >> 5;            // 0..7
    const int r0   = (lane >> 2) + (w << 3); // 0..63
    const int q0   = lane & 3;            // 0..3
    #pragma unroll
    for (int rr = 0; rr < NR; rr += 64) {
        const int r = r0 + rr;
        const float4* srow = reinterpret_cast<const float4*>(src + (size_t)r * ND);
        #pragma unroll
        for (int s2 = 0; s2 < 16; ++s2) {
            float4 v = srow[q0 + (s2 << 2)];
            const int k = ((s2 << 2) + q0) << 2;   // 4*quad
            dst[(k+0)*NR + r] = v.x;
            dst[(k+1)*NR + r] = v.y;
            dst[(k+2)*NR + r] = v.z;
            dst[(k+3)*NR + r] = v.w;
        }
    }
}

// -------- kernel 1: projections (C = A @ W^T), 64x64 tiles, K=256 resident --------
__global__ void proj_kernel(const float* __restrict__ eeg,
                            const float* __restrict__ eye,
                            const float* __restrict__ Weeg,
                            const float* __restrict__ Weye) {
    extern __shared__ float sm[];
    float* A_s = sm;              // [256][64] transposed
    float* W_s = sm + 256*64;     // [256][64] transposed
    const int z = blockIdx.z;
    const float* A = z ? eye  : eeg;
    const float* W = z ? Weye : Weeg;
    float* C       = z ? g_v  : g_e;
    const int rbase = blockIdx.x * 64;
    const int nbase = blockIdx.y * 64;
    const int tid = threadIdx.x;

    load_tile_T<64>(A_s, A + (size_t)rbase * ND, tid);
    load_tile_T<64>(W_s, W + (size_t)nbase * ND, tid);
    __syncthreads();

    const int tx = tid & 15, ty = tid >> 4;
    float acc[4][4];
    #pragma unroll
    for (int i = 0; i < 4; i++)
        #pragma unroll
        for (int j = 0; j < 4; j++) acc[i][j] = 0.f;

    #pragma unroll 4
    for (int k = 0; k < 256; ++k) {
        float4 a = *reinterpret_cast<const float4*>(&A_s[k*64 + ty*4]);
        float4 b = *reinterpret_cast<const float4*>(&W_s[k*64 + tx*4]);
        float av[4] = {a.x, a.y, a.z, a.w};
        float bv[4] = {b.x, b.y, b.z, b.w};
        #pragma unroll
        for (int i = 0; i < 4; i++)
            #pragma unroll
            for (int j = 0; j < 4; j++)
                acc[i][j] = fmaf(av[i], bv[j], acc[i][j]);
    }

    #pragma unroll
    for (int i = 0; i < 4; i++) {
        float4 o = make_float4(acc[i][0], acc[i][1], acc[i][2], acc[i][3]);
        *reinterpret_cast<float4*>(&C[(size_t)(rbase + ty*4 + i) * ND + nbase + tx*4]) = o;
    }
}

// -------- kernel 2: L2 normalize in place (warp per row); fold 1/TEMP into e --------
__global__ void norm_kernel() {
    const int row  = blockIdx.x * 8 + (threadIdx.x >> 5);
    const int lane = threadIdx.x & 31;
    float extra;
    float* base;
    if (row < NROWS) { base = g_e + (size_t)row * ND; extra = 1.0f / 0.07f; }
    else             { base = g_v + (size_t)(row - NROWS) * ND; extra = 1.0f; }
    float4* p = reinterpret_cast<float4*>(base);
    float4 x0 = p[lane];
    float4 x1 = p[lane + 32];
    float ss = x0.x*x0.x + x0.y*x0.y + x0.z*x0.z + x0.w*x0.w
             + x1.x*x1.x + x1.y*x1.y + x1.z*x1.z + x1.w*x1.w;
    #pragma unroll
    for (int o = 16; o > 0; o >>= 1) ss += __shfl_xor_sync(0xffffffffu, ss, o);
    const float s = extra / fmaxf(sqrtf(ss), 1e-12f);
    x0.x *= s; x0.y *= s; x0.z *= s; x0.w *= s;
    x1.x *= s; x1.y *= s; x1.z *= s; x1.w *= s;
    p[lane]      = x0;
    p[lane + 32] = x1;
}

// -------- kernel 3: per-batch inclusive scan of valid -> rank --------
__global__ void rank_kernel(const int* __restrict__ mask) {
    __shared__ int sc[NT];
    const int b = blockIdx.x, t = threadIdx.x;
    sc[t] = (mask[b*NT + t] > 0) ? 1 : 0;
    __syncthreads();
    for (int off = 1; off < NT; off <<= 1) {
        int add = (t >= off) ? sc[t - off] : 0;
        __syncthreads();
        sc[t] += add;
        __syncthreads();
    }
    g_rank[b*NT + t] = sc[t] - 1;
}

// -------- kernel 4: sims tiles + fused banded posmax + online logsumexp --------
// block = 256 threads, tile 64 rows x (8 x 128 col tiles), K=256 resident.
__global__ void sims_kernel(const int* __restrict__ mask) {
    extern __shared__ float sm[];
    float* e_s  = sm;                     // 256*64
    float* v_s  = e_s + 256*64;           // 256*128
    float* redA = v_s + 256*128;          // 64*17
    float* redB = redA + 64*17;           // 64*17
    float* m_st = redB + 64*17;           // 64 running max
    float* s_st = m_st + 64;              // 64 running sumexp
    float* p_st = s_st + 64;              // 64 running posmax
    int* rrank_s  = reinterpret_cast<int*>(p_st + 64);  // 64
    int* rvalid_s = rrank_s + 64;                        // 64
    int* cv_s     = rvalid_s + 64;                       // 128
    int* cr_s     = cv_s + 128;                          // 128

    const int b     = blockIdx.y;
    const int rbase = blockIdx.x * 64;
    const int tid   = threadIdx.x;
    const int tx = tid & 15, ty = tid >> 4;
    const float* Eb = g_e + ((size_t)b*NT + rbase) * ND;
    const float* Vb = g_v + (size_t)b*NT*ND;

    load_tile_T<64>(e_s, Eb, tid);
    if (tid < 64) {
        m_st[tid] = -1e30f; s_st[tid] = 0.f; p_st[tid] = -1e30f;
        rvalid_s[tid] = (mask[b*NT + rbase + tid] > 0);
        rrank_s[tid]  = g_rank[b*NT + rbase + tid];
    }

    for (int jt = 0; jt < 8; ++jt) {
        const int jbase = jt * 128;
        __syncthreads();   // v_s free; init/e_s visible on first iter
        load_tile_T<128>(v_s, Vb + (size_t)jbase * ND, tid);
        if (tid < 128) {
            cv_s[tid] = (mask[b*NT + jbase + tid] > 0);
            cr_s[tid] = g_rank[b*NT + jbase + tid];
        }
        __syncthreads();

        float acc[4][8];
        #pragma unroll
        for (int i = 0; i < 4; i++)
            #pragma unroll
            for (int j = 0; j < 8; j++) acc[i][j] = 0.f;

        #pragma unroll 2
        for (int k = 0; k < 256; ++k) {
            float4 a  = *reinterpret_cast<const float4*>(&e_s[k*64  + ty*4]);
            float4 b0 = *reinterpret_cast<const float4*>(&v_s[k*128 + tx*8]);
            float4 b1 = *reinterpret_cast<const float4*>(&v_s[k*128 + tx*8 + 4]);
            float av[4] = {a.x, a.y, a.z, a.w};
            float bv[8] = {b0.x, b0.y, b0.z, b0.w, b1.x, b1.y, b1.z, b1.w};
            #pragma unroll
            for (int i = 0; i < 4; i++)
                #pragma unroll
                for (int j = 0; j < 8; j++)
                    acc[i][j] = fmaf(av[i], bv[j], acc[i][j]);
        }

        int my_r[4];
        #pragma unroll
        for (int i = 0; i < 4; i++) my_r[i] = rrank_s[ty*4 + i];

        float tmax[4], pmax[4];
        #pragma unroll
        for (int i = 0; i < 4; i++) { tmax[i] = -1e30f; pmax[i] = -1e30f; }
        #pragma unroll
        for (int j = 0; j < 8; j++) {
            const int c = tx*8 + j;
            if (cv_s[c]) {
                const int rj = cr_s[c];
                #pragma unroll
                for (int i = 0; i < 4; i++) {
                    const float v = acc[i][j];
                    tmax[i] = fmaxf(tmax[i], v);
                    const int d = my_r[i] - rj;
                    if (d >= -2 && d <= 2) pmax[i] = fmaxf(pmax[i], v);
                }
            }
        }
        #pragma unroll
        for (int i = 0; i < 4; i++) {
            redA[(ty*4 + i)*17 + tx] = tmax[i];
            redB[(ty*4 + i)*17 + tx] = pmax[i];
        }
        __syncthreads();
        if (tid < 64) {
            float tm = -1e30f, pm = -1e30f;
            #pragma unroll
            for (int x = 0; x < 16; x++) {
                tm = fmaxf(tm, redA[tid*17 + x]);
                pm = fmaxf(pm, redB[tid*17 + x]);
            }
            p_st[tid] = fmaxf(p_st[tid], pm);
            const float mo = m_st[tid];
            const float mn = fmaxf(mo, tm);
            s_st[tid] *= __expf(mo - mn);
            m_st[tid] = mn;
        }
        __syncthreads();
        float mrow[4];
        #pragma unroll
        for (int i = 0; i < 4; i++) mrow[i] = m_st[ty*4 + i];
        float ps[4] = {0.f, 0.f, 0.f, 0.f};
        #pragma unroll
        for (int j = 0; j < 8; j++) {
            const int c = tx*8 + j;
            if (cv_s[c]) {
                #pragma unroll
                for (int i = 0; i < 4; i++)
                    ps[i] += __expf(acc[i][j] - mrow[i]);
            }
        }
        #pragma unroll
        for (int i = 0; i < 4; i++) redA[(ty*4 + i)*17 + tx] = ps[i];
        __syncthreads();
        if (tid < 64) {
            float sum = 0.f;
            #pragma unroll
            for (int x = 0; x < 16; x++) sum += redA[tid*17 + x];
            s_st[tid] += sum;
        }
    }
    __syncthreads();
    if (tid < 64) {
        float outv = 0.f;
        if (rvalid_s[tid])
            outv = (m_st[tid] + logf(s_st[tid])) - p_st[tid];  // lse - posmax
        g_row[b*NT + rbase + tid] = outv;
    }
}

// -------- kernel 5: final reduction to scalar --------
__global__ void finalize_kernel(const int* __restrict__ mask, float* __restrict__ out) {
    __shared__ float sb[32];
    const int w = threadIdx.x >> 5, lane = threadIdx.x & 31;
    float sum = 0.f; int tv = 0;
    for (int t = lane; t < NT; t += 32) {
        sum += g_row[w*NT + t];
        tv  += (mask[w*NT + t] > 0) ? 1 : 0;
    }
    #pragma unroll
    for (int o = 16; o > 0; o >>= 1) {
        sum += __shfl_xor_sync(0xffffffffu, sum, o);
        tv  += __shfl_xor_sync(0xffffffffu, tv, o);
    }
    if (lane == 0) sb[w] = (tv >= 2) ? (sum / (float)tv) : 0.f;
    __syncthreads();
    if (threadIdx.x == 0) {
        float tot = 0.f;
        for (int i = 0; i < 32; i++) tot += sb[i];
        out[0] = tot / (32.0f + 1e-8f);
    }
}

extern "C" void kernel_launch(void* const* d_in, const int* in_sizes, int n_in,
                              void* d_out, int out_size) {
    const float* eeg  = (const float*)d_in[0];
    const float* eye  = (const float*)d_in[1];
    const int*   mask = (const int*)d_in[2];
    const float* Weeg = (const float*)d_in[3];
    const float* Weye = (const float*)d_in[4];
    float* out = (float*)d_out;

    const int PROJ_SMEM = (2 * 256 * 64) * 4;                          // 128 KB
    const int SIMS_SMEM = (256*64 + 256*128 + 2*64*17 + 3*64) * 4
                        + (64 + 64 + 128 + 128) * 4;                   // ~203 KB

    cudaFuncSetAttribute(proj_kernel, cudaFuncAttributeMaxDynamicSharedMemorySize, PROJ_SMEM);
    cudaFuncSetAttribute(sims_kernel, cudaFuncAttributeMaxDynamicSharedMemorySize, SIMS_SMEM);

    proj_kernel<<<dim3(NROWS/64, ND/64, 2), 256, PROJ_SMEM>>>(eeg, eye, Weeg, Weye);
    norm_kernel<<<(2 * NROWS) / 8, 256>>>();
    rank_kernel<<<NB, NT>>>(mask);
    sims_kernel<<<dim3(NT/64, NB), 256, SIMS_SMEM>>>(mask);
    finalize_kernel<<<1, 1024>>>(mask, out);
}

// round 6
// speedup vs baseline: 2.5171x; 2.5171x over previous
#include <cuda_runtime.h>
#include <cstdint>
#include <math.h>

#define NB 32
#define NT 1024
#define ND 256
#define NROWS (NB*NT)
#define SENT 0x7FFFFFFF

// -------- scratch (device globals; no allocation) --------
__device__ float g_e[NROWS*ND];   // projected+normalized eeg (scaled by 1/TEMP)
__device__ float g_v[NROWS*ND];   // projected+normalized eye
__device__ int   g_rank[NROWS];   // compressed rank per (b,t)
__device__ float g_row[NROWS];    // per-row masked loss

// ======================= helpers =======================
__device__ __forceinline__ uint32_t f2tf(float f) {
    uint32_t u; asm("cvt.rna.tf32.f32 %0, %1;" : "=r"(u) : "f"(f)); return u;
}
__device__ __forceinline__ void mma8(float* c, const uint32_t* a, const uint32_t* b) {
    asm volatile("mma.sync.aligned.m16n8k8.row.col.f32.tf32.tf32.f32 "
        "{%0,%1,%2,%3}, {%4,%5,%6,%7}, {%8,%9}, {%0,%1,%2,%3};"
        : "+f"(c[0]), "+f"(c[1]), "+f"(c[2]), "+f"(c[3])
        : "r"(a[0]), "r"(a[1]), "r"(a[2]), "r"(a[3]), "r"(b[0]), "r"(b[1]));
}
__device__ __forceinline__ float qmax(float v) {
    v = fmaxf(v, __shfl_xor_sync(0xffffffffu, v, 1));
    v = fmaxf(v, __shfl_xor_sync(0xffffffffu, v, 2));
    return v;
}
__device__ __forceinline__ float qsum(float v) {
    v += __shfl_xor_sync(0xffffffffu, v, 1);
    v += __shfl_xor_sync(0xffffffffu, v, 2);
    return v;
}

// Copy R x COLS fp32 slab (gmem row stride ldg) into smem rows of stride SP
// (floats), rounding each value to tf32 (rna). SP % 32 == 4 keeps the mma
// fragment loads conflict-free.
template<int R, int COLS, int NTHR>
__device__ __forceinline__ void load_slab(float* __restrict__ dst, int SP,
                                          const float* __restrict__ src, int ldg,
                                          int tid) {
    constexpr int CV = COLS / 4;
    constexpr int NV = R * CV;
    #pragma unroll 4
    for (int i = tid; i < NV; i += NTHR) {
        const int r  = i / CV;
        const int c4 = (i - r * CV) << 2;
        float4 v = *reinterpret_cast<const float4*>(src + (size_t)r * ldg + c4);
        uint32_t* u = reinterpret_cast<uint32_t*>(&v);
        u[0] = f2tf(v.x); u[1] = f2tf(v.y); u[2] = f2tf(v.z); u[3] = f2tf(v.w);
        *reinterpret_cast<float4*>(dst + r * SP + c4) = v;
    }
}

// ======================= kernel 1: proj + L2-normalize (tf32 mma.sync) =======================
// Per block: C[64 x 256] = A[64 x 256] @ W^T, K split in 2 smem halves.
// 8 warps as 2(row) x 4(col); warp tile 32 x 64. Full rows in-block -> fused L2 norm.
__global__ __launch_bounds__(256, 1)
void proj_kernel(const float* __restrict__ eeg, const float* __restrict__ eye,
                 const float* __restrict__ Weeg, const float* __restrict__ Weye) {
    extern __shared__ float sm[];
    float* A_s   = sm;                 // [64][132]
    float* W_s   = sm + 64 * 132;      // [256][132]
    float* ssq_s = W_s + 256 * 132;    // [64][4]
    const int tid = threadIdx.x, wid = tid >> 5, lane = tid & 31;
    const int g = lane >> 2, t = lane & 3;
    const int wm = wid >> 2, wn = wid & 3;
    const int z = blockIdx.y;
    const float* src = z ? eye  : eeg;
    const float* W   = z ? Weye : Weeg;
    float* dst       = z ? g_v  : g_e;
    const float extra = z ? 1.0f : (1.0f / 0.07f);
    const int rbase = blockIdx.x * 64;

    float acc[2][8][4];
    #pragma unroll
    for (int mt = 0; mt < 2; mt++)
        #pragma unroll
        for (int nt = 0; nt < 8; nt++)
            #pragma unroll
            for (int q = 0; q < 4; q++) acc[mt][nt][q] = 0.f;

    #pragma unroll 1
    for (int kh = 0; kh < 2; ++kh) {
        if (kh) __syncthreads();
        load_slab<64, 128, 256>(A_s, 132, src + (size_t)rbase * ND + kh * 128, ND, tid);
        load_slab<256, 128, 256>(W_s, 132, W + kh * 128, ND, tid);
        __syncthreads();
        #pragma unroll
        for (int ks = 0; ks < 16; ++ks) {
            const int kb = ks * 8;
            uint32_t a[2][4];
            #pragma unroll
            for (int mt = 0; mt < 2; ++mt) {
                const float* Ar = A_s + (wm * 32 + mt * 16 + g) * 132 + kb + t;
                a[mt][0] = __float_as_uint(Ar[0]);
                a[mt][1] = __float_as_uint(Ar[8 * 132]);
                a[mt][2] = __float_as_uint(Ar[4]);
                a[mt][3] = __float_as_uint(Ar[8 * 132 + 4]);
            }
            #pragma unroll
            for (int nt = 0; nt < 8; ++nt) {
                const float* Br = W_s + (wn * 64 + nt * 8 + g) * 132 + kb + t;
                uint32_t b[2] = { __float_as_uint(Br[0]), __float_as_uint(Br[4]) };
                mma8(acc[0][nt], a[0], b);
                mma8(acc[1][nt], a[1], b);
            }
        }
    }
    __syncthreads();

    // per-row sum of squares: lane holds rows {g, g+8} of 2 m-tiles, 16 cols each
    float ssq[2][2] = {{0.f, 0.f}, {0.f, 0.f}};
    #pragma unroll
    for (int mt = 0; mt < 2; ++mt)
        #pragma unroll
        for (int nt = 0; nt < 8; ++nt) {
            ssq[mt][0] = fmaf(acc[mt][nt][0], acc[mt][nt][0], ssq[mt][0]);
            ssq[mt][0] = fmaf(acc[mt][nt][1], acc[mt][nt][1], ssq[mt][0]);
            ssq[mt][1] = fmaf(acc[mt][nt][2], acc[mt][nt][2], ssq[mt][1]);
            ssq[mt][1] = fmaf(acc[mt][nt][3], acc[mt][nt][3], ssq[mt][1]);
        }
    #pragma unroll
    for (int mt = 0; mt < 2; ++mt)
        #pragma unroll
        for (int rg = 0; rg < 2; ++rg)
            ssq[mt][rg] = qsum(ssq[mt][rg]);
    if (t == 0) {
        #pragma unroll
        for (int mt = 0; mt < 2; ++mt)
            #pragma unroll
            for (int rg = 0; rg < 2; ++rg)
                ssq_s[(wm * 32 + mt * 16 + g + 8 * rg) * 4 + wn] = ssq[mt][rg];
    }
    __syncthreads();
    #pragma unroll
    for (int mt = 0; mt < 2; ++mt)
        #pragma unroll
        for (int rg = 0; rg < 2; ++rg) {
            const int row = wm * 32 + mt * 16 + g + 8 * rg;
            const float s = ssq_s[row * 4 + 0] + ssq_s[row * 4 + 1]
                          + ssq_s[row * 4 + 2] + ssq_s[row * 4 + 3];
            const float sc = extra / fmaxf(sqrtf(s), 1e-12f);
            float* orow = dst + (size_t)(rbase + row) * ND + wn * 64;
            #pragma unroll
            for (int nt = 0; nt < 8; ++nt) {
                float2 o;
                o.x = acc[mt][nt][2 * rg + 0] * sc;
                o.y = acc[mt][nt][2 * rg + 1] * sc;
                *reinterpret_cast<float2*>(orow + nt * 8 + 2 * t) = o;
            }
        }
}

// ======================= kernel 2: per-batch rank scan =======================
__global__ void rank_kernel(const int* __restrict__ mask) {
    __shared__ int sc[NT];
    const int b = blockIdx.x, t = threadIdx.x;
    sc[t] = (mask[b * NT + t] > 0) ? 1 : 0;
    __syncthreads();
    for (int off = 1; off < NT; off <<= 1) {
        int add = (t >= off) ? sc[t - off] : 0;
        __syncthreads();
        sc[t] += add;
        __syncthreads();
    }
    g_rank[b * NT + t] = sc[t] - 1;
}

// ======================= kernel 3: sims (tf32 mma.sync) + fused softmax =======================
// Per block: e-tile [128 x 256] smem-resident; loop 8 v col-tiles x 2 K-halves.
// 8 warps as 4(row) x 2(col); warp tile 32 x 64; register accumulators.
// Row stats (online max / sumexp / banded posmax) quad-reduced, replicated in
// registers across jt; cross-warp merge at the end.
__global__ __launch_bounds__(256, 1)
void sims_kernel(const int* __restrict__ mask) {
    extern __shared__ float sm[];
    float* E_s   = sm;                              // [128][260]
    float* V_s   = E_s + 128 * 260;                 // [128][132]
    int*   cvr_s = reinterpret_cast<int*>(V_s + 128 * 132);  // [128] rank-or-sentinel
    float* mrg   = reinterpret_cast<float*>(cvr_s + 128);    // [128][2][3]
    const int tid = threadIdx.x, wid = tid >> 5, lane = tid & 31;
    const int g = lane >> 2, t = lane & 3;
    const int wm = wid >> 1, wn = wid & 1;
    const int b = blockIdx.y, rbase = blockIdx.x * 128;

    load_slab<128, 256, 256>(E_s, 260, g_e + ((size_t)b * NT + rbase) * ND, ND, tid);

    int rr[2][2];
    #pragma unroll
    for (int mt = 0; mt < 2; ++mt)
        #pragma unroll
        for (int rg = 0; rg < 2; ++rg)
            rr[mt][rg] = g_rank[b * NT + rbase + wm * 32 + mt * 16 + g + 8 * rg];

    float rm[2][2], rs[2][2], rp[2][2];
    #pragma unroll
    for (int mt = 0; mt < 2; ++mt)
        #pragma unroll
        for (int rg = 0; rg < 2; ++rg) { rm[mt][rg] = -1e30f; rs[mt][rg] = 0.f; rp[mt][rg] = -1e30f; }

    #pragma unroll 1
    for (int jt = 0; jt < 8; ++jt) {
        const int jbase = jt * 128;
        float acc[2][8][4];
        #pragma unroll
        for (int mt = 0; mt < 2; mt++)
            #pragma unroll
            for (int nt = 0; nt < 8; nt++)
                #pragma unroll
                for (int q = 0; q < 4; q++) acc[mt][nt][q] = 0.f;

        #pragma unroll 1
        for (int kh = 0; kh < 2; ++kh) {
            __syncthreads();   // everyone done with previous V_s / cvr_s contents
            load_slab<128, 128, 256>(V_s, 132,
                g_v + ((size_t)b * NT + jbase) * ND + kh * 128, ND, tid);
            if (kh == 0 && tid < 128) {
                const int gj = b * NT + jbase + tid;
                cvr_s[tid] = (mask[gj] > 0) ? g_rank[gj] : SENT;
            }
            __syncthreads();
            #pragma unroll
            for (int ks = 0; ks < 16; ++ks) {
                const int kb = ks * 8;
                uint32_t a[2][4];
                #pragma unroll
                for (int mt = 0; mt < 2; ++mt) {
                    const float* Ar = E_s + (wm * 32 + mt * 16 + g) * 260 + kh * 128 + kb + t;
                    a[mt][0] = __float_as_uint(Ar[0]);
                    a[mt][1] = __float_as_uint(Ar[8 * 260]);
                    a[mt][2] = __float_as_uint(Ar[4]);
                    a[mt][3] = __float_as_uint(Ar[8 * 260 + 4]);
                }
                #pragma unroll
                for (int nt = 0; nt < 8; ++nt) {
                    const float* Br = V_s + (wn * 64 + nt * 8 + g) * 132 + kb + t;
                    uint32_t bb[2] = { __float_as_uint(Br[0]), __float_as_uint(Br[4]) };
                    mma8(acc[0][nt], a[0], bb);
                    mma8(acc[1][nt], a[1], bb);
                }
            }
        }

        // fused epilogue: my 16 cols per row-slot
        int cv[8][2];
        #pragma unroll
        for (int nt = 0; nt < 8; ++nt) {
            cv[nt][0] = cvr_s[wn * 64 + nt * 8 + 2 * t];
            cv[nt][1] = cvr_s[wn * 64 + nt * 8 + 2 * t + 1];
        }
        #pragma unroll
        for (int mt = 0; mt < 2; ++mt)
            #pragma unroll
            for (int rg = 0; rg < 2; ++rg) {
                float tm = -1e30f, pm = -1e30f;
                #pragma unroll
                for (int nt = 0; nt < 8; ++nt)
                    #pragma unroll
                    for (int h = 0; h < 2; ++h) {
                        const int c = cv[nt][h];
                        if (c != SENT) {
                            const float v = acc[mt][nt][2 * rg + h];
                            tm = fmaxf(tm, v);
                            const int d = rr[mt][rg] - c;
                            if (d >= -2 && d <= 2) pm = fmaxf(pm, v);
                        }
                    }
                tm = qmax(tm); pm = qmax(pm);
                rp[mt][rg] = fmaxf(rp[mt][rg], pm);
                const float mn = fmaxf(rm[mt][rg], tm);
                float sum = 0.f;
                #pragma unroll
                for (int nt = 0; nt < 8; ++nt)
                    #pragma unroll
                    for (int h = 0; h < 2; ++h)
                        if (cv[nt][h] != SENT)
                            sum += __expf(acc[mt][nt][2 * rg + h] - mn);
                sum = qsum(sum);
                rs[mt][rg] = rs[mt][rg] * __expf(rm[mt][rg] - mn) + sum;
                rm[mt][rg] = mn;
            }
    }

    if (t == 0) {
        #pragma unroll
        for (int mt = 0; mt < 2; ++mt)
            #pragma unroll
            for (int rg = 0; rg < 2; ++rg) {
                const int row = wm * 32 + mt * 16 + g + 8 * rg;
                mrg[(row * 2 + wn) * 3 + 0] = rm[mt][rg];
                mrg[(row * 2 + wn) * 3 + 1] = rs[mt][rg];
                mrg[(row * 2 + wn) * 3 + 2] = rp[mt][rg];
            }
    }
    __syncthreads();
    if (tid < 128) {
        const int row = tid;
        const float m0 = mrg[(row * 2) * 3 + 0], s0 = mrg[(row * 2) * 3 + 1], p0 = mrg[(row * 2) * 3 + 2];
        const float m1 = mrg[(row * 2 + 1) * 3 + 0], s1 = mrg[(row * 2 + 1) * 3 + 1], p1 = mrg[(row * 2 + 1) * 3 + 2];
        const float m = fmaxf(m0, m1);
        const float s = s0 * __expf(m0 - m) + s1 * __expf(m1 - m);
        const float p = fmaxf(p0, p1);
        const int gi = b * NT + rbase + row;
        float outv = 0.f;
        if (mask[gi] > 0) outv = (m + logf(s)) - p;   // lse - posmax
        g_row[gi] = outv;
    }
}

// ======================= kernel 4: final reduction to scalar =======================
__global__ void finalize_kernel(const int* __restrict__ mask, float* __restrict__ out) {
    __shared__ float sbuf[32];
    const int w = threadIdx.x >> 5, lane = threadIdx.x & 31;
    float sum = 0.f; int tv = 0;
    for (int t = lane; t < NT; t += 32) {
        sum += g_row[w * NT + t];
        tv  += (mask[w * NT + t] > 0) ? 1 : 0;
    }
    #pragma unroll
    for (int o = 16; o > 0; o >>= 1) {
        sum += __shfl_xor_sync(0xffffffffu, sum, o);
        tv  += __shfl_xor_sync(0xffffffffu, tv, o);
    }
    if (lane == 0) sbuf[w] = (tv >= 2) ? (sum / (float)tv) : 0.f;
    __syncthreads();
    if (threadIdx.x == 0) {
        float tot = 0.f;
        for (int i = 0; i < 32; i++) tot += sbuf[i];
        out[0] = tot / (32.0f + 1e-8f);
    }
}

extern "C" void kernel_launch(void* const* d_in, const int* in_sizes, int n_in,
                              void* d_out, int out_size) {
    const float* eeg  = (const float*)d_in[0];
    const float* eye  = (const float*)d_in[1];
    const int*   mask = (const int*)d_in[2];
    const float* Weeg = (const float*)d_in[3];
    const float* Weye = (const float*)d_in[4];
    float* out = (float*)d_out;

    const int PROJ_SMEM = (64 * 132 + 256 * 132 + 64 * 4) * 4;                 // ~170 KB
    const int SIMS_SMEM = (128 * 260 + 128 * 132) * 4 + 128 * 4 + 128 * 2 * 3 * 4;  // ~204 KB

    cudaFuncSetAttribute(proj_kernel, cudaFuncAttributeMaxDynamicSharedMemorySize, PROJ_SMEM);
    cudaFuncSetAttribute(sims_kernel, cudaFuncAttributeMaxDynamicSharedMemorySize, SIMS_SMEM);

    proj_kernel<<<dim3(NROWS / 64, 2), 256, PROJ_SMEM>>>(eeg, eye, Weeg, Weye);
    rank_kernel<<<NB, NT>>>(mask);
    sims_kernel<<<dim3(NT / 128, NB), 256, SIMS_SMEM>>>(mask);
    finalize_kernel<<<1, 1024>>>(mask, out);
}

// round 7
// speedup vs baseline: 5.6652x; 2.2507x over previous
#include <cuda_runtime.h>
#include <cuda_bf16.h>
#include <cstdint>
#include <math.h>

#define NB 32
#define NT 1024
#define ND 256
#define NROWS (NB*NT)
#define SENT 0x7FFFFFFF
#define SP2 132   // b32 stride per smem row (128 data + 4 pad; 132 % 32 == 4 -> conflict-free)

// -------- scratch (device globals; no allocation) --------
__device__ uint32_t g_eb[NROWS*ND/2];  // e (normalized, x1/TEMP) as packed bf16x2
__device__ uint32_t g_vb[NROWS*ND/2];  // v (normalized) as packed bf16x2
__device__ int      g_rank[NROWS];
__device__ float    g_row[NROWS];
__device__ float    g_pb[NB];

// ======================= helpers =======================
__device__ __forceinline__ uint32_t smem_u32(const void* p) {
    uint32_t a;
    asm("{ .reg .u64 t; cvta.to.shared.u64 t, %1; cvt.u32.u64 %0, t; }" : "=r"(a) : "l"(p));
    return a;
}
__device__ __forceinline__ uint32_t f2tf(float f) {
    uint32_t u; asm("cvt.rna.tf32.f32 %0, %1;" : "=r"(u) : "f"(f)); return u;
}
__device__ __forceinline__ void mma8(float* c, const uint32_t* a, const uint32_t* b) {
    asm volatile("mma.sync.aligned.m16n8k8.row.col.f32.tf32.tf32.f32 "
        "{%0,%1,%2,%3}, {%4,%5,%6,%7}, {%8,%9}, {%0,%1,%2,%3};"
        : "+f"(c[0]), "+f"(c[1]), "+f"(c[2]), "+f"(c[3])
        : "r"(a[0]), "r"(a[1]), "r"(a[2]), "r"(a[3]), "r"(b[0]), "r"(b[1]));
}
__device__ __forceinline__ void mma16(float* c, const uint32_t* a, const uint32_t* b) {
    asm volatile("mma.sync.aligned.m16n8k16.row.col.f32.bf16.bf16.f32 "
        "{%0,%1,%2,%3}, {%4,%5,%6,%7}, {%8,%9}, {%0,%1,%2,%3};"
        : "+f"(c[0]), "+f"(c[1]), "+f"(c[2]), "+f"(c[3])
        : "r"(a[0]), "r"(a[1]), "r"(a[2]), "r"(a[3]), "r"(b[0]), "r"(b[1]));
}
__device__ __forceinline__ void cpa16(uint32_t dst, const void* src) {
    asm volatile("cp.async.cg.shared.global [%0], [%1], 16;" :: "r"(dst), "l"(src) : "memory");
}
__device__ __forceinline__ float qmax(float v) {
    v = fmaxf(v, __shfl_xor_sync(0xffffffffu, v, 1));
    v = fmaxf(v, __shfl_xor_sync(0xffffffffu, v, 2));
    return v;
}
__device__ __forceinline__ float qsum(float v) {
    v += __shfl_xor_sync(0xffffffffu, v, 1);
    v += __shfl_xor_sync(0xffffffffu, v, 2);
    return v;
}
__device__ __forceinline__ uint32_t packbf2(float x, float y) {
    __nv_bfloat162 h = __floats2bfloat162_rn(x, y);  // x -> low, y -> high
    return *reinterpret_cast<uint32_t*>(&h);
}

// fp32 gmem slab -> smem rows (stride SP floats), rounded to tf32. SP%32==4.
template<int R, int COLS, int NTHR>
__device__ __forceinline__ void load_slab(float* __restrict__ dst, int SP,
                                          const float* __restrict__ src, int ldg,
                                          int tid) {
    constexpr int CV = COLS / 4;
    constexpr int NV = R * CV;
    #pragma unroll 4
    for (int i = tid; i < NV; i += NTHR) {
        const int r  = i / CV;
        const int c4 = (i - r * CV) << 2;
        float4 v = *reinterpret_cast<const float4*>(src + (size_t)r * ldg + c4);
        uint32_t* u = reinterpret_cast<uint32_t*>(&v);
        u[0] = f2tf(v.x); u[1] = f2tf(v.y); u[2] = f2tf(v.z); u[3] = f2tf(v.w);
        *reinterpret_cast<float4*>(dst + r * SP + c4) = v;
    }
}

// ======================= kernel 1: proj + L2-normalize (tf32) -> bf16 out =======================
__global__ __launch_bounds__(256, 1)
void proj_kernel(const float* __restrict__ eeg, const float* __restrict__ eye,
                 const float* __restrict__ Weeg, const float* __restrict__ Weye) {
    extern __shared__ float sm[];
    float* A_s   = sm;                 // [64][132]
    float* W_s   = sm + 64 * 132;      // [256][132]
    float* ssq_s = W_s + 256 * 132;    // [64][4]
    const int tid = threadIdx.x, wid = tid >> 5, lane = tid & 31;
    const int g = lane >> 2, t = lane & 3;
    const int wm = wid >> 2, wn = wid & 3;
    const int z = blockIdx.y;
    const float* src = z ? eye  : eeg;
    const float* W   = z ? Weye : Weeg;
    uint32_t* dst    = z ? g_vb : g_eb;
    const float extra = z ? 1.0f : (1.0f / 0.07f);
    const int rbase = blockIdx.x * 64;

    float acc[2][8][4];
    #pragma unroll
    for (int mt = 0; mt < 2; mt++)
        #pragma unroll
        for (int nt = 0; nt < 8; nt++)
            #pragma unroll
            for (int q = 0; q < 4; q++) acc[mt][nt][q] = 0.f;

    #pragma unroll 1
    for (int kh = 0; kh < 2; ++kh) {
        if (kh) __syncthreads();
        load_slab<64, 128, 256>(A_s, 132, src + (size_t)rbase * ND + kh * 128, ND, tid);
        load_slab<256, 128, 256>(W_s, 132, W + kh * 128, ND, tid);
        __syncthreads();
        #pragma unroll
        for (int ks = 0; ks < 16; ++ks) {
            const int kb = ks * 8;
            uint32_t a[2][4];
            #pragma unroll
            for (int mt = 0; mt < 2; ++mt) {
                const float* Ar = A_s + (wm * 32 + mt * 16 + g) * 132 + kb + t;
                a[mt][0] = __float_as_uint(Ar[0]);
                a[mt][1] = __float_as_uint(Ar[8 * 132]);
                a[mt][2] = __float_as_uint(Ar[4]);
                a[mt][3] = __float_as_uint(Ar[8 * 132 + 4]);
            }
            #pragma unroll
            for (int nt = 0; nt < 8; ++nt) {
                const float* Br = W_s + (wn * 64 + nt * 8 + g) * 132 + kb + t;
                uint32_t b[2] = { __float_as_uint(Br[0]), __float_as_uint(Br[4]) };
                mma8(acc[0][nt], a[0], b);
                mma8(acc[1][nt], a[1], b);
            }
        }
    }
    __syncthreads();

    float ssq[2][2] = {{0.f, 0.f}, {0.f, 0.f}};
    #pragma unroll
    for (int mt = 0; mt < 2; ++mt)
        #pragma unroll
        for (int nt = 0; nt < 8; ++nt) {
            ssq[mt][0] = fmaf(acc[mt][nt][0], acc[mt][nt][0], ssq[mt][0]);
            ssq[mt][0] = fmaf(acc[mt][nt][1], acc[mt][nt][1], ssq[mt][0]);
            ssq[mt][1] = fmaf(acc[mt][nt][2], acc[mt][nt][2], ssq[mt][1]);
            ssq[mt][1] = fmaf(acc[mt][nt][3], acc[mt][nt][3], ssq[mt][1]);
        }
    #pragma unroll
    for (int mt = 0; mt < 2; ++mt)
        #pragma unroll
        for (int rg = 0; rg < 2; ++rg)
            ssq[mt][rg] = qsum(ssq[mt][rg]);
    if (t == 0) {
        #pragma unroll
        for (int mt = 0; mt < 2; ++mt)
            #pragma unroll
            for (int rg = 0; rg < 2; ++rg)
                ssq_s[(wm * 32 + mt * 16 + g + 8 * rg) * 4 + wn] = ssq[mt][rg];
    }
    __syncthreads();
    #pragma unroll
    for (int mt = 0; mt < 2; ++mt)
        #pragma unroll
        for (int rg = 0; rg < 2; ++rg) {
            const int row = wm * 32 + mt * 16 + g + 8 * rg;
            const float s = ssq_s[row * 4 + 0] + ssq_s[row * 4 + 1]
                          + ssq_s[row * 4 + 2] + ssq_s[row * 4 + 3];
            const float sc = extra / fmaxf(sqrtf(s), 1e-12f);
            uint32_t* orow = dst + (size_t)(rbase + row) * (ND / 2) + wn * 32;
            #pragma unroll
            for (int nt = 0; nt < 8; ++nt)
                orow[nt * 4 + t] = packbf2(acc[mt][nt][2 * rg + 0] * sc,
                                           acc[mt][nt][2 * rg + 1] * sc);
        }
}

// ======================= kernel 2: per-batch rank scan =======================
__global__ void rank_kernel(const int* __restrict__ mask) {
    __shared__ int sc[NT];
    const int b = blockIdx.x, t = threadIdx.x;
    sc[t] = (mask[b * NT + t] > 0) ? 1 : 0;
    __syncthreads();
    for (int off = 1; off < NT; off <<= 1) {
        int add = (t >= off) ? sc[t - off] : 0;
        __syncthreads();
        sc[t] += add;
        __syncthreads();
    }
    g_rank[b * NT + t] = sc[t] - 1;
}

// ======================= kernel 3: sims (bf16 m16n8k16) + fused softmax =======================
// Block: 128 rows; E [128 x 256] bf16 resident; V double-buffered 128-col tiles (full K),
// prefetched with cp.async. 8 warps as 4(row) x 2(col), warp tile 32 x 64.
__global__ __launch_bounds__(256, 1)
void sims_kernel(const int* __restrict__ mask) {
    extern __shared__ char smc[];
    uint32_t* E2  = reinterpret_cast<uint32_t*>(smc);       // 128 x SP2
    uint32_t* V2  = E2 + 128 * SP2;                         // 2 x 128 x SP2
    int*      cvr = reinterpret_cast<int*>(V2 + 2 * 128 * SP2);  // [1024]
    float*    mrg = reinterpret_cast<float*>(cvr + NT);     // [128][2][3]
    const uint32_t sbE = smem_u32(smc);
    const uint32_t sbV = sbE + 128 * SP2 * 4;

    const int tid = threadIdx.x, wid = tid >> 5, lane = tid & 31;
    const int g = lane >> 2, t = lane & 3;
    const int wm = wid >> 1, wn = wid & 1;
    const int b = blockIdx.y, rbase = blockIdx.x * 128;

    for (int i = tid; i < NT; i += 256) {
        const int gj = b * NT + i;
        cvr[i] = (mask[gj] > 0) ? g_rank[gj] : SENT;
    }
    // E tile + V tile 0 via cp.async (gmem rows 512B -> smem rows 528B)
    const char* ebase = reinterpret_cast<const char*>(g_eb) + (size_t)(b * NT + rbase) * 512;
    const char* vbase = reinterpret_cast<const char*>(g_vb) + (size_t)b * NT * 512;
    #pragma unroll 4
    for (int i = tid; i < 4096; i += 256) {
        const int r = i >> 5, ch = i & 31;
        cpa16(sbE + r * 528 + ch * 16, ebase + (size_t)r * 512 + ch * 16);
    }
    #pragma unroll 4
    for (int i = tid; i < 4096; i += 256) {
        const int r = i >> 5, ch = i & 31;
        cpa16(sbV + r * 528 + ch * 16, vbase + (size_t)r * 512 + ch * 16);
    }
    asm volatile("cp.async.commit_group;" ::: "memory");

    int rr[2][2];
    float rm[2][2], rs[2][2], rp[2][2];
    #pragma unroll
    for (int mt = 0; mt < 2; ++mt)
        #pragma unroll
        for (int rg = 0; rg < 2; ++rg) {
            rr[mt][rg] = g_rank[b * NT + rbase + wm * 32 + mt * 16 + g + 8 * rg];
            rm[mt][rg] = -1e30f; rs[mt][rg] = 0.f; rp[mt][rg] = -1e30f;
        }

    #pragma unroll 1
    for (int jt = 0; jt < 8; ++jt) {
        asm volatile("cp.async.wait_group 0;" ::: "memory");
        __syncthreads();   // tile jt ready; all warps done reading buffer (jt+1)&1
        if (jt < 7) {
            const char* vsrc = vbase + (size_t)(jt + 1) * 128 * 512;
            const uint32_t vdst = sbV + ((jt + 1) & 1) * 128 * 528;
            #pragma unroll 4
            for (int i = tid; i < 4096; i += 256) {
                const int r = i >> 5, ch = i & 31;
                cpa16(vdst + r * 528 + ch * 16, vsrc + (size_t)r * 512 + ch * 16);
            }
            asm volatile("cp.async.commit_group;" ::: "memory");
        }
        const uint32_t* Vb2 = V2 + (jt & 1) * 128 * SP2;
        float acc[2][8][4];
        #pragma unroll
        for (int mt = 0; mt < 2; mt++)
            #pragma unroll
            for (int nt = 0; nt < 8; nt++)
                #pragma unroll
                for (int q = 0; q < 4; q++) acc[mt][nt][q] = 0.f;

        const uint32_t* Ab = E2  + (wm * 32 + g) * SP2 + t;
        const uint32_t* Bb = Vb2 + (wn * 64 + g) * SP2 + t;
        #pragma unroll
        for (int ks = 0; ks < 16; ++ks) {
            const int kb = ks * 8;
            uint32_t a[2][4];
            #pragma unroll
            for (int mt = 0; mt < 2; ++mt) {
                const uint32_t* Ar = Ab + mt * 16 * SP2 + kb;
                a[mt][0] = Ar[0];
                a[mt][1] = Ar[8 * SP2];
                a[mt][2] = Ar[4];
                a[mt][3] = Ar[8 * SP2 + 4];
            }
            #pragma unroll
            for (int nt = 0; nt < 8; ++nt) {
                const uint32_t* Br = Bb + nt * 8 * SP2 + kb;
                uint32_t bb[2] = { Br[0], Br[4] };
                mma16(acc[0][nt], a[0], bb);
                mma16(acc[1][nt], a[1], bb);
            }
        }

        // fused epilogue
        const int jbase = jt * 128;
        int cv[8][2];
        #pragma unroll
        for (int nt = 0; nt < 8; ++nt) {
            cv[nt][0] = cvr[jbase + wn * 64 + nt * 8 + 2 * t];
            cv[nt][1] = cvr[jbase + wn * 64 + nt * 8 + 2 * t + 1];
        }
        #pragma unroll
        for (int mt = 0; mt < 2; ++mt)
            #pragma unroll
            for (int rg = 0; rg < 2; ++rg) {
                float tm = -1e30f, pm = -1e30f;
                #pragma unroll
                for (int nt = 0; nt < 8; ++nt)
                    #pragma unroll
                    for (int h = 0; h < 2; ++h) {
                        const int c = cv[nt][h];
                        if (c != SENT) {
                            const float v = acc[mt][nt][2 * rg + h];
                            tm = fmaxf(tm, v);
                            const int d = rr[mt][rg] - c;
                            if (d >= -2 && d <= 2) pm = fmaxf(pm, v);
                        }
                    }
                tm = qmax(tm); pm = qmax(pm);
                rp[mt][rg] = fmaxf(rp[mt][rg], pm);
                const float mn = fmaxf(rm[mt][rg], tm);
                float sum = 0.f;
                #pragma unroll
                for (int nt = 0; nt < 8; ++nt)
                    #pragma unroll
                    for (int h = 0; h < 2; ++h)
                        if (cv[nt][h] != SENT)
                            sum += __expf(acc[mt][nt][2 * rg + h] - mn);
                sum = qsum(sum);
                rs[mt][rg] = rs[mt][rg] * __expf(rm[mt][rg] - mn) + sum;
                rm[mt][rg] = mn;
            }
    }

    if (t == 0) {
        #pragma unroll
        for (int mt = 0; mt < 2; ++mt)
            #pragma unroll
            for (int rg = 0; rg < 2; ++rg) {
                const int row = wm * 32 + mt * 16 + g + 8 * rg;
                mrg[(row * 2 + wn) * 3 + 0] = rm[mt][rg];
                mrg[(row * 2 + wn) * 3 + 1] = rs[mt][rg];
                mrg[(row * 2 + wn) * 3 + 2] = rp[mt][rg];
            }
    }
    __syncthreads();
    if (tid < 128) {
        const int row = tid;
        const float m0 = mrg[(row * 2) * 3 + 0], s0 = mrg[(row * 2) * 3 + 1], p0 = mrg[(row * 2) * 3 + 2];
        const float m1 = mrg[(row * 2 + 1) * 3 + 0], s1 = mrg[(row * 2 + 1) * 3 + 1], p1 = mrg[(row * 2 + 1) * 3 + 2];
        const float m = fmaxf(m0, m1);
        const float s = s0 * __expf(m0 - m) + s1 * __expf(m1 - m);
        const float p = fmaxf(p0, p1);
        const int gi = b * NT + rbase + row;
        float outv = 0.f;
        if (mask[gi] > 0) outv = (m + logf(s)) - p;   // lse - posmax
        g_row[gi] = outv;
    }
}

// ======================= kernels 4/5: reduction =======================
__global__ void fin1_kernel() {
    __shared__ float sbuf[8];
    const int b = blockIdx.x, tid = threadIdx.x, w = tid >> 5, lane = tid & 31;
    float sum = 0.f;
    for (int t = tid; t < NT; t += 256) sum += g_row[b * NT + t];
    #pragma unroll
    for (int o = 16; o > 0; o >>= 1) sum += __shfl_xor_sync(0xffffffffu, sum, o);
    if (lane == 0) sbuf[w] = sum;
    __syncthreads();
    if (tid == 0) {
        float tot = 0.f;
        #pragma unroll
        for (int i = 0; i < 8; i++) tot += sbuf[i];
        const int Tv = g_rank[b * NT + NT - 1] + 1;
        g_pb[b] = (Tv >= 2) ? (tot / (float)Tv) : 0.f;
    }
}
__global__ void fin2_kernel(float* __restrict__ out) {
    float v = g_pb[threadIdx.x];
    #pragma unroll
    for (int o = 16; o > 0; o >>= 1) v += __shfl_xor_sync(0xffffffffu, v, o);
    if (threadIdx.x == 0) out[0] = v / (32.0f + 1e-8f);
}

extern "C" void kernel_launch(void* const* d_in, const int* in_sizes, int n_in,
                              void* d_out, int out_size) {
    const float* eeg  = (const float*)d_in[0];
    const float* eye  = (const float*)d_in[1];
    const int*   mask = (const int*)d_in[2];
    const float* Weeg = (const float*)d_in[3];
    const float* Weye = (const float*)d_in[4];
    float* out = (float*)d_out;

    const int PROJ_SMEM = (64 * 132 + 256 * 132 + 64 * 4) * 4;                  // ~169 KB
    const int SIMS_SMEM = 3 * 128 * SP2 * 4 + NT * 4 + 128 * 2 * 3 * 4;         // 209920 B

    cudaFuncSetAttribute(proj_kernel, cudaFuncAttributeMaxDynamicSharedMemorySize, PROJ_SMEM);
    cudaFuncSetAttribute(sims_kernel, cudaFuncAttributeMaxDynamicSharedMemorySize, SIMS_SMEM);

    proj_kernel<<<dim3(NROWS / 64, 2), 256, PROJ_SMEM>>>(eeg, eye, Weeg, Weye);
    rank_kernel<<<NB, NT>>>(mask);
    sims_kernel<<<dim3(NT / 128, NB), 256, SIMS_SMEM>>>(mask);
    fin1_kernel<<<NB, 256>>>();
    fin2_kernel<<<1, 32>>>(out);
}